// round 5
// baseline (speedup 1.0000x reference)
#include <cuda_runtime.h>
#include <cuda_bf16.h>
#include <cstdint>

#define NPROTO 64
#define PDIM   512
#define NFEAT  200000
#define EPSN   1e-8f
#define NACC   148                      // persistent CTAs (== #partial slices)
#define TILE   256
#define NTILE  ((NFEAT + TILE - 1) / TILE)   // 782 (781 full + 64-row tail)

// ---------------- device scratch (static; no allocation) ----------------
// Prototypes normalized, bf16, pre-permuted for mma B-fragments:
// g_PbP[(proto*32 + ks)*4 + q] = { bf16x2(P[k][16ks+2q..]), bf16x2(P[k][16ks+8+2q..]) }
__device__ uint2 g_PbP[NPROTO * 32 * 4];
__device__ float g_Partial[NACC * NPROTO * PDIM];   // per-CTA segment sums (~19.4 MB)
__device__ int   g_Cnt[NPROTO];                     // global counts (int atomics = deterministic)

// ---------------- kernel 1: normalize prototypes -> permuted bf16; zero counts ----------------
__global__ void prep_kernel(const float* __restrict__ P) {
    int k = blockIdx.x;          // 64 blocks
    int t = threadIdx.x;         // 128 threads
    const float* row = P + k * PDIM;
    if (t == 0) g_Cnt[k] = 0;    // re-zeroed every replay, before fused kernel runs

    float ss = 0.f;
    #pragma unroll
    for (int i = 0; i < 4; ++i) { float v = row[t + 128 * i]; ss += v * v; }
    __shared__ float red[4];
    #pragma unroll
    for (int o = 16; o > 0; o >>= 1) ss += __shfl_xor_sync(0xffffffffu, ss, o);
    if ((t & 31) == 0) red[t >> 5] = ss;
    __syncthreads();
    float norm = sqrtf(red[0] + red[1] + red[2] + red[3]);
    float inv = 1.f / fmaxf(norm, EPSN);

    int ks = t >> 2, q = t & 3;
    int i0 = ks * 8 + q;
    float2 fa = make_float2(row[2 * i0] * inv,       row[2 * i0 + 1] * inv);
    float2 fb = make_float2(row[2 * (i0 + 4)] * inv, row[2 * (i0 + 4) + 1] * inv);
    __nv_bfloat162 ha = __float22bfloat162_rn(fa);
    __nv_bfloat162 hb = __float22bfloat162_rn(fb);
    uint2 u;
    u.x = *reinterpret_cast<uint32_t*>(&ha);
    u.y = *reinterpret_cast<uint32_t*>(&hb);
    g_PbP[(k * 32 + ks) * 4 + q] = u;
}

// ---------------- kernel 2: FUSED sims+argmax+segment-sum, single DRAM pass ----------------
// 148 persistent CTAs x 512 threads. smem: [64][512] fp32 accumulator + 256B assignments.
// Per 256-row tile: phase A — warp w computes sims for rows w*16..w*16+15 vs all 64 protos
// via m16n8k16 bf16 mma + argmax -> s_asg. phase B — thread t owns column t, re-reads the
// tile rows (L2 hits) and accumulates into the smem accumulator. No atomics in hot loop.
__global__ __launch_bounds__(512) void fused_kernel(const float* __restrict__ F) {
    extern __shared__ float acc[];                         // NPROTO*PDIM floats
    unsigned char* s_asg = (unsigned char*)(acc + NPROTO * PDIM);  // 256 bytes, 8B-aligned

    int t = threadIdx.x;
    #pragma unroll
    for (int i = 0; i < NPROTO; ++i) acc[i * PDIM + t] = 0.f;

    int w = t >> 5, lane = t & 31;
    int q = lane & 3, rg = lane >> 2;
    const float2* F2 = reinterpret_cast<const float2*>(F);
    int cnt = 0;
    __syncthreads();

    for (int tile = blockIdx.x; tile < NTILE; tile += NACC) {
        int rbase = tile * TILE;

        // ---------- phase A: sims (16 rows x 64 protos per warp) ----------
        float a_[8][4];
        #pragma unroll
        for (int n = 0; n < 8; ++n) { a_[n][0] = a_[n][1] = a_[n][2] = a_[n][3] = 0.f; }

        int r0 = rbase + w * 16 + rg;
        int r1 = r0 + 8;
        size_t bA0 = (size_t)(r0 < NFEAT ? r0 : NFEAT - 1) * (PDIM / 2);
        size_t bA1 = (size_t)(r1 < NFEAT ? r1 : NFEAT - 1) * (PDIM / 2);

        #pragma unroll 2
        for (int ks = 0; ks < 32; ++ks) {
            int ko = ks * 8 + q;
            float2 f0 = F2[bA0 + ko];
            float2 f1 = F2[bA1 + ko];
            float2 f2 = F2[bA0 + ko + 4];
            float2 f3 = F2[bA1 + ko + 4];
            uint32_t A0, A1, A2, A3;
            { __nv_bfloat162 h = __float22bfloat162_rn(f0); A0 = *reinterpret_cast<uint32_t*>(&h); }
            { __nv_bfloat162 h = __float22bfloat162_rn(f1); A1 = *reinterpret_cast<uint32_t*>(&h); }
            { __nv_bfloat162 h = __float22bfloat162_rn(f2); A2 = *reinterpret_cast<uint32_t*>(&h); }
            { __nv_bfloat162 h = __float22bfloat162_rn(f3); A3 = *reinterpret_cast<uint32_t*>(&h); }
            #pragma unroll
            for (int nb = 0; nb < 8; ++nb) {
                uint2 bb = g_PbP[((nb * 8 + rg) * 32 + ks) * 4 + q];
                asm volatile(
                    "mma.sync.aligned.m16n8k16.row.col.f32.bf16.bf16.f32 "
                    "{%0,%1,%2,%3}, {%4,%5,%6,%7}, {%8,%9}, {%0,%1,%2,%3};"
                    : "+f"(a_[nb][0]), "+f"(a_[nb][1]), "+f"(a_[nb][2]), "+f"(a_[nb][3])
                    : "r"(A0), "r"(A1), "r"(A2), "r"(A3), "r"(bb.x), "r"(bb.y));
            }
        }

        // argmax over 64 protos; lane holds protos {nb*8+2q, +1} for rows rg (d0,d1), rg+8 (d2,d3)
        #pragma unroll
        for (int half = 0; half < 2; ++half) {
            float bv = -3.0e38f; int bi = 0;
            #pragma unroll
            for (int nb = 0; nb < 8; ++nb) {
                #pragma unroll
                for (int j = 0; j < 2; ++j) {
                    float v = a_[nb][half * 2 + j];
                    int p = nb * 8 + 2 * q + j;
                    if (v > bv) { bv = v; bi = p; }
                }
            }
            #pragma unroll
            for (int off = 1; off <= 2; off <<= 1) {
                float ov = __shfl_xor_sync(0xffffffffu, bv, off);
                int   oi = __shfl_xor_sync(0xffffffffu, bi, off);
                if (ov > bv || (ov == bv && oi < bi)) { bv = ov; bi = oi; }
            }
            if (q == 0) s_asg[w * 16 + half * 8 + rg] = (unsigned char)bi;
        }
        __syncthreads();

        // ---------- phase B: accumulate tile rows (L2 hits) into smem ----------
        int valid = NFEAT - rbase; if (valid > TILE) valid = TILE;   // 256 or 64
        for (int r = 0; r < valid; r += 16) {
            unsigned long long a8a = *reinterpret_cast<const unsigned long long*>(s_asg + r);
            unsigned long long a8b = *reinterpret_cast<const unsigned long long*>(s_asg + r + 8);
            float v[16];
            #pragma unroll
            for (int j = 0; j < 16; ++j) v[j] = F[(size_t)(rbase + r + j) * PDIM + t];
            #pragma unroll
            for (int j = 0; j < 8; ++j) {
                int a = (int)((a8a >> (8 * j)) & 255ull);
                acc[a * PDIM + t] += v[j];
            }
            #pragma unroll
            for (int j = 0; j < 8; ++j) {
                int a = (int)((a8b >> (8 * j)) & 255ull);
                acc[a * PDIM + t] += v[8 + j];
            }
            if (t < NPROTO) {
                #pragma unroll
                for (int j = 0; j < 8; ++j) cnt += (int)(((a8a >> (8 * j)) & 255ull) == (unsigned long long)t);
                #pragma unroll
                for (int j = 0; j < 8; ++j) cnt += (int)(((a8b >> (8 * j)) & 255ull) == (unsigned long long)t);
            }
        }
        __syncthreads();   // protect s_asg before next tile's phase A
    }

    // deterministic flush of this CTA's partial slice
    float* part = g_Partial + (size_t)blockIdx.x * (NPROTO * PDIM);
    #pragma unroll 4
    for (int k = 0; k < NPROTO; ++k) part[k * PDIM + t] = acc[k * PDIM + t];
    if (t < NPROTO) atomicAdd(&g_Cnt[t], cnt);   // int atomic: order-independent, deterministic
}

// ---------------- kernel 3: reduce partials + EMA update ----------------
__global__ void finalize_kernel(const float* __restrict__ P, float* __restrict__ out) {
    int k = blockIdx.x >> 2;                          // 64 protos x 4 col-groups
    int t = ((blockIdx.x & 3) << 7) + threadIdx.x;    // 128 threads -> column
    float s = 0.f;
    #pragma unroll 4
    for (int b = 0; b < NACC; ++b)
        s += g_Partial[(size_t)b * (NPROTO * PDIM) + k * PDIM + t];
    int c = g_Cnt[k];
    float p = P[k * PDIM + t];
    float mean = s / fmaxf((float)c, 1.f);
    out[k * PDIM + t] = (c > 0) ? (0.9f * p + 0.1f * mean) : p;
}

// ---------------- launch ----------------
extern "C" void kernel_launch(void* const* d_in, const int* in_sizes, int n_in,
                              void* d_out, int out_size) {
    const float* F = (const float*)d_in[0];
    const float* P = (const float*)d_in[1];
    if (in_sizes[0] == NPROTO * PDIM) {     // robust to input order
        F = (const float*)d_in[1];
        P = (const float*)d_in[0];
    }

    prep_kernel<<<NPROTO, 128>>>(P);

    int smem = NPROTO * PDIM * (int)sizeof(float) + 256;
    cudaFuncSetAttribute(fused_kernel, cudaFuncAttributeMaxDynamicSharedMemorySize, smem);
    fused_kernel<<<NACC, 512, smem>>>(F);

    finalize_kernel<<<NPROTO * 4, 128>>>(P, (float*)d_out);
}

// round 7
// speedup vs baseline: 1.8698x; 1.8698x over previous
#include <cuda_runtime.h>
#include <cuda_bf16.h>
#include <cstdint>

#define NPROTO 64
#define PDIM   512
#define NFEAT  200000
#define EPSN   1e-8f
#define NACC   148                       // persistent CTAs (== #partial slices)
#define CHUNK  32                        // rows per staged chunk
#define NCHUNK (NFEAT / CHUNK)           // 6250, exact (no tail)

// ---------------- device scratch (static; no allocation) ----------------
// B fragments, coalesced: g_B[(nblk*32+ks)*32 + lane], lane = rg*4+q holds
// { bf16x2(Pn[16ks+2q..]), bf16x2(Pn[16ks+8+2q..]) } for proto n = nblk*8+rg.
__device__ uint2 g_B[8 * 32 * 32];
__device__ float g_Partial[NACC * NPROTO * PDIM];   // per-CTA segment sums (~19.4 MB)
__device__ int   g_Cnt[NPROTO];

__device__ __forceinline__ uint32_t smem_u32(const void* p) {
    uint32_t a;
    asm("{ .reg .u64 t; cvta.to.shared.u64 t, %1; cvt.u32.u64 %0, t; }" : "=r"(a) : "l"(p));
    return a;
}

// ---------------- kernel 1: normalize prototypes -> coalesced bf16 frags ----------------
__global__ void prep_kernel(const float* __restrict__ P) {
    int k = blockIdx.x;          // 64 blocks (one proto each)
    int t = threadIdx.x;         // 128 threads
    const float* row = P + k * PDIM;
    if (t == 0) g_Cnt[k] = 0;    // re-zeroed every replay before fused kernel

    float ss = 0.f;
    #pragma unroll
    for (int i = 0; i < 4; ++i) { float v = row[t + 128 * i]; ss += v * v; }
    __shared__ float red[4];
    #pragma unroll
    for (int o = 16; o > 0; o >>= 1) ss += __shfl_xor_sync(0xffffffffu, ss, o);
    if ((t & 31) == 0) red[t >> 5] = ss;
    __syncthreads();
    float norm = sqrtf(red[0] + red[1] + red[2] + red[3]);
    float inv = 1.f / fmaxf(norm, EPSN);

    int ks = t >> 2, q = t & 3;                    // 32 ksteps x 4 q
    int i0 = ks * 8 + q;                           // float2 index in row
    float2 fa = make_float2(row[2 * i0] * inv,       row[2 * i0 + 1] * inv);
    float2 fb = make_float2(row[2 * (i0 + 4)] * inv, row[2 * (i0 + 4) + 1] * inv);
    __nv_bfloat162 ha = __float22bfloat162_rn(fa);
    __nv_bfloat162 hb = __float22bfloat162_rn(fb);
    uint2 u;
    u.x = *reinterpret_cast<uint32_t*>(&ha);
    u.y = *reinterpret_cast<uint32_t*>(&hb);
    // lane = (k%8)*4 + q, nblk = k/8
    g_B[((k >> 3) * 32 + ks) * 32 + (k & 7) * 4 + q] = u;
}

// ---------------- kernel 2: FUSED, wavefront-clean, reduced reg pressure ----------------
// 148 persistent CTAs x 512 threads. smem: acc[64][512] f32 (128KB) +
// staged A chunk 32x512 bf16 swizzled (32KB) + argmax candidates + assignments.
// Pipeline per chunk: prefetched bf16 regs -> STS staged -> [prefetch+convert next]
// -> ldmatrix+mma (B resident in regs) -> argmax -> accumulate from staged smem.
__global__ __launch_bounds__(512) void fused_kernel(const float* __restrict__ F) {
    extern __shared__ float acc[];                        // 64*512 f32
    char*  s_A   = (char*)(acc + NPROTO * PDIM);          // 32 rows * 1024B, swizzled
    float* candV = (float*)(s_A + CHUNK * 1024);          // [8][32]
    int*   candI = (int*)(candV + 8 * 32);                // [8][32]
    unsigned char* s_asg = (unsigned char*)(candI + 8 * 32);  // 32B, 8B-aligned

    int t = threadIdx.x;
    int w = t >> 5, lane = t & 31;
    int pg = w & 7;                 // proto-group (nblk): protos pg*8..pg*8+7
    int rb = w >> 3;                // row-block: rows rb*16..rb*16+15 of chunk
    int q = lane & 3, rg = lane >> 2;

    #pragma unroll
    for (int i = 0; i < NPROTO; ++i) acc[i * PDIM + t] = 0.f;

    // resident B fragments: one nblk per warp, 32 ks x uint2 = 64 regs
    uint2 Bf[32];
    #pragma unroll
    for (int ks = 0; ks < 32; ++ks) Bf[ks] = g_B[(pg * 32 + ks) * 32 + lane];

    // ldmatrix lane addressing (constant per thread)
    int rowB = rb * 16 + (lane & 8) + (lane & 7);          // row in 32-row buffer
    int halfSel = (lane >> 4) & 1;                         // 16B half of 16-col group
    uint32_t sA32 = smem_u32(s_A);

    const float4* F4 = reinterpret_cast<const float4*>(F);
    int cnt = 0;

    // prologue prefetch + convert: chunk ci0, 8 x float4 -> 8 x uint2 (bf16x4)
    int ci = blockIdx.x;
    uint2 u[8];
    #pragma unroll
    for (int j = 0; j < 8; ++j) {
        float4 v = F4[(size_t)ci * (CHUNK * 128) + j * 512 + t];
        __nv_bfloat162 h0 = __float22bfloat162_rn(make_float2(v.x, v.y));
        __nv_bfloat162 h1 = __float22bfloat162_rn(make_float2(v.z, v.w));
        u[j].x = *reinterpret_cast<uint32_t*>(&h0);
        u[j].y = *reinterpret_cast<uint32_t*>(&h1);
    }

    __syncthreads();

    for (; ci < NCHUNK; ci += NACC) {
        // ---- stage current chunk: bf16 regs -> swizzled smem ----
        #pragma unroll
        for (int j = 0; j < 8; ++j) {
            int idx = j * 512 + t;            // 0..4095 float4s
            int row = idx >> 7;               // 128 float4 per row
            int c4  = idx & 127;
            int i16 = c4 >> 1;
            int sw = (i16 & ~7) | ((i16 ^ row) & 7);
            *reinterpret_cast<uint2*>(s_A + row * 1024 + sw * 16 + (c4 & 1) * 8) = u[j];
        }
        __syncthreads();

        // ---- prefetch + convert next chunk (latency hidden behind phases A+B) ----
        int cn = ci + NACC;
        if (cn < NCHUNK) {
            #pragma unroll
            for (int j = 0; j < 8; ++j) {
                float4 v = F4[(size_t)cn * (CHUNK * 128) + j * 512 + t];
                __nv_bfloat162 h0 = __float22bfloat162_rn(make_float2(v.x, v.y));
                __nv_bfloat162 h1 = __float22bfloat162_rn(make_float2(v.z, v.w));
                u[j].x = *reinterpret_cast<uint32_t*>(&h0);
                u[j].y = *reinterpret_cast<uint32_t*>(&h1);
            }
        }

        // ---- phase A: ldmatrix + mma, 16 rows x 8 protos per warp ----
        float d0 = 0.f, d1 = 0.f, d2 = 0.f, d3 = 0.f;
        #pragma unroll
        for (int ks = 0; ks < 32; ++ks) {
            int i16 = ks * 2 + halfSel;
            int sw = (i16 & ~7) | ((i16 ^ rowB) & 7);
            uint32_t addr = sA32 + rowB * 1024 + sw * 16;
            uint32_t a0, a1, a2, a3;
            asm volatile("ldmatrix.sync.aligned.m8n8.x4.shared.b16 {%0,%1,%2,%3}, [%4];"
                         : "=r"(a0), "=r"(a1), "=r"(a2), "=r"(a3) : "r"(addr));
            asm volatile(
                "mma.sync.aligned.m16n8k16.row.col.f32.bf16.bf16.f32 "
                "{%0,%1,%2,%3}, {%4,%5,%6,%7}, {%8,%9}, {%0,%1,%2,%3};"
                : "+f"(d0), "+f"(d1), "+f"(d2), "+f"(d3)
                : "r"(a0), "r"(a1), "r"(a2), "r"(a3), "r"(Bf[ks].x), "r"(Bf[ks].y));
        }

        // per-warp argmax over its 8 protos (lane holds cols 2q, 2q+1 of rows rg, rg+8)
        #pragma unroll
        for (int half = 0; half < 2; ++half) {
            float bv; int bi;
            {
                float e0 = half ? d2 : d0;
                float e1 = half ? d3 : d1;
                bv = e0; bi = pg * 8 + 2 * q;
                if (e1 > bv) { bv = e1; bi = pg * 8 + 2 * q + 1; }
            }
            #pragma unroll
            for (int off = 1; off <= 2; off <<= 1) {
                float ov = __shfl_xor_sync(0xffffffffu, bv, off);
                int   oi = __shfl_xor_sync(0xffffffffu, bi, off);
                if (ov > bv || (ov == bv && oi < bi)) { bv = ov; bi = oi; }
            }
            if (q == 0) {
                int r32 = rb * 16 + half * 8 + rg;
                candV[pg * 32 + r32] = bv;
                candI[pg * 32 + r32] = bi;
            }
        }
        __syncthreads();

        // cross-group reduce (ascending pg, strict > keeps lowest index on ties)
        if (t < CHUNK) {
            float bv = candV[t]; int bi = candI[t];
            #pragma unroll
            for (int g = 1; g < 8; ++g) {
                float ov = candV[g * 32 + t];
                if (ov > bv) { bv = ov; bi = candI[g * 32 + t]; }
            }
            s_asg[t] = (unsigned char)bi;
        }
        __syncthreads();

        // ---- phase B: accumulate staged bf16 into smem accumulator ----
        unsigned long long a8[4];
        #pragma unroll
        for (int j = 0; j < 4; ++j)
            a8[j] = *reinterpret_cast<const unsigned long long*>(s_asg + j * 8);

        int i16t = t >> 3, inoff = (t & 7) * 2;
        #pragma unroll
        for (int r = 0; r < CHUNK; ++r) {
            int sw = (i16t & ~7) | ((i16t ^ r) & 7);
            __nv_bfloat16 hv = *reinterpret_cast<const __nv_bfloat16*>(
                s_A + r * 1024 + sw * 16 + inoff);
            int a = (int)((a8[r >> 3] >> ((r & 7) * 8)) & 255ull);
            acc[a * PDIM + t] += __bfloat162float(hv);
        }
        if (t < NPROTO) {
            #pragma unroll
            for (int j = 0; j < 4; ++j) {
                unsigned long long x = a8[j];
                #pragma unroll
                for (int b = 0; b < 8; ++b)
                    cnt += (int)(((x >> (8 * b)) & 255ull) == (unsigned long long)t);
            }
        }
        __syncthreads();   // staging + s_asg free for next chunk
    }

    // deterministic flush of this CTA's partial slice
    float* part = g_Partial + (size_t)blockIdx.x * (NPROTO * PDIM);
    #pragma unroll 4
    for (int k = 0; k < NPROTO; ++k) part[k * PDIM + t] = acc[k * PDIM + t];
    if (t < NPROTO) atomicAdd(&g_Cnt[t], cnt);   // int atomics: deterministic
}

// ---------------- kernel 3: reduce partials + EMA update ----------------
__global__ void finalize_kernel(const float* __restrict__ P, float* __restrict__ out) {
    int k = blockIdx.x >> 3;                          // 64 protos x 8 col-groups
    int t = ((blockIdx.x & 7) << 6) + threadIdx.x;    // 64 threads -> column
    float s = 0.f;
    #pragma unroll 8
    for (int b = 0; b < NACC; ++b)
        s += g_Partial[(size_t)b * (NPROTO * PDIM) + k * PDIM + t];
    int c = g_Cnt[k];
    float p = P[k * PDIM + t];
    float mean = s / fmaxf((float)c, 1.f);
    out[k * PDIM + t] = (c > 0) ? (0.9f * p + 0.1f * mean) : p;
}

// ---------------- launch ----------------
extern "C" void kernel_launch(void* const* d_in, const int* in_sizes, int n_in,
                              void* d_out, int out_size) {
    const float* F = (const float*)d_in[0];
    const float* P = (const float*)d_in[1];
    if (in_sizes[0] == NPROTO * PDIM) {     // robust to input order
        F = (const float*)d_in[1];
        P = (const float*)d_in[0];
    }

    prep_kernel<<<NPROTO, 128>>>(P);

    int smem = NPROTO * PDIM * (int)sizeof(float)   // 128 KB accumulator
             + CHUNK * 1024                         // 32 KB staged A
             + 8 * 32 * (int)sizeof(float)          // candV
             + 8 * 32 * (int)sizeof(int)            // candI
             + 32;                                  // s_asg
    cudaFuncSetAttribute(fused_kernel, cudaFuncAttributeMaxDynamicSharedMemorySize, smem);
    fused_kernel<<<NACC, 512, smem>>>(F);

    finalize_kernel<<<NPROTO * 8, 64>>>(P, (float*)d_out);
}

// round 10
// speedup vs baseline: 1.9844x; 1.0613x over previous
#include <cuda_runtime.h>
#include <cuda_bf16.h>
#include <cstdint>

#define NPROTO 64
#define PDIM   512
#define NFEAT  200000
#define EPSN   1e-8f
#define NACC   148                       // persistent CTAs (== #partial slices)
#define CHUNK  32                        // rows per staged chunk
#define NCHUNK (NFEAT / CHUNK)           // 6250, exact (no tail)

// ---------------- device scratch (static; no allocation) ----------------
// B fragments, coalesced: g_B[(nblk*32+ks)*32 + lane], lane = rg*4+q holds
// { bf16x2(Pn[16ks+2q..]), bf16x2(Pn[16ks+8+2q..]) } for proto n = nblk*8+rg.
__device__ uint2 g_B[8 * 32 * 32];
__device__ float g_Partial[NACC * NPROTO * PDIM];   // per-CTA segment sums (~19.4 MB)
__device__ int   g_Cnt[NPROTO];

__device__ __forceinline__ uint32_t smem_u32(const void* p) {
    uint32_t a;
    asm("{ .reg .u64 t; cvta.to.shared.u64 t, %1; cvt.u32.u64 %0, t; }" : "=r"(a) : "l"(p));
    return a;
}

// ---------------- kernel 1: normalize prototypes -> coalesced bf16 frags ----------------
__global__ void prep_kernel(const float* __restrict__ P) {
    int k = blockIdx.x;          // 64 blocks (one proto each)
    int t = threadIdx.x;         // 128 threads
    const float* row = P + k * PDIM;
    if (t == 0) g_Cnt[k] = 0;    // re-zeroed every replay before fused kernel

    float ss = 0.f;
    #pragma unroll
    for (int i = 0; i < 4; ++i) { float v = row[t + 128 * i]; ss += v * v; }
    __shared__ float red[4];
    #pragma unroll
    for (int o = 16; o > 0; o >>= 1) ss += __shfl_xor_sync(0xffffffffu, ss, o);
    if ((t & 31) == 0) red[t >> 5] = ss;
    __syncthreads();
    float norm = sqrtf(red[0] + red[1] + red[2] + red[3]);
    float inv = 1.f / fmaxf(norm, EPSN);

    int ks = t >> 2, q = t & 3;                    // 32 ksteps x 4 q
    int i0 = ks * 8 + q;                           // float2 index in row
    float2 fa = make_float2(row[2 * i0] * inv,       row[2 * i0 + 1] * inv);
    float2 fb = make_float2(row[2 * (i0 + 4)] * inv, row[2 * (i0 + 4) + 1] * inv);
    __nv_bfloat162 ha = __float22bfloat162_rn(fa);
    __nv_bfloat162 hb = __float22bfloat162_rn(fb);
    uint2 u;
    u.x = *reinterpret_cast<uint32_t*>(&ha);
    u.y = *reinterpret_cast<uint32_t*>(&hb);
    g_B[((k >> 3) * 32 + ks) * 32 + (k & 7) * 4 + q] = u;
}

// ---------------- kernel 2: FUSED, software-pipelined, uniform warps ----------------
// 148 persistent CTAs x 512 threads, 2 __syncthreads per chunk.
// Per chunk k: stage(k)->buf[k&1]; S1; prefetch(k+1); {MMA(k) || accumulate(k-1)}
// in ONE phase (warps overlap tensor + smem pipes); S2; reduce cand -> s_asg[k&1].
__global__ __launch_bounds__(512) void fused_kernel(const float* __restrict__ F) {
    extern __shared__ float acc[];                        // 64*512 f32 = 128 KB
    char*  s_A   = (char*)(acc + NPROTO * PDIM);          // 2 bufs x 32 rows x 1024B
    float* candV = (float*)(s_A + 2 * CHUNK * 1024);      // [8][32]
    int*   candI = (int*)(candV + 8 * 32);                // [8][32]
    unsigned char* s_asg = (unsigned char*)(candI + 8 * 32);  // [2][32], 8B-aligned

    int t = threadIdx.x;
    #pragma unroll
    for (int i = 0; i < NPROTO; ++i) acc[i * PDIM + t] = 0.f;

    int w = t >> 5, lane = t & 31;
    int pg = w & 7;                       // proto group (protos pg*8..pg*8+7)
    int rb = w >> 3;                      // row block (rows rb*16..rb*16+15)
    int q = lane & 3, rg = lane >> 2;
    int rowB = rb * 16 + (lane & 15);     // ldmatrix row
    int halfSel = lane >> 4;              // 16B half selector
    uint32_t sA0 = smem_u32(s_A);

    // resident B fragments: one proto group per warp (64 regs)
    uint2 Bf[32];
    #pragma unroll
    for (int ks = 0; ks < 32; ++ks) Bf[ks] = g_B[(pg * 32 + ks) * 32 + lane];

    // accumulate addressing: thread t -> rows half rh, column pair cp
    int rh = t >> 8;                      // 0/1 -> rows rh*16..rh*16+15
    int cp = t & 255;                     // float2 column pair (cols 2cp, 2cp+1)
    int i16c = cp >> 2, inoffc = (cp & 3) * 4;
    float2* accp = reinterpret_cast<float2*>(acc);

    const float4* F4 = reinterpret_cast<const float4*>(F);
    int n = (NCHUNK - blockIdx.x + NACC - 1) / NACC;      // 42 or 43 chunks
    int cnt = 0;

    // prologue: prefetch + convert chunk 0 (8 x LDG.128 per thread, coalesced)
    uint2 u[8];
    {
        size_t cb = (size_t)blockIdx.x * (CHUNK * 128);
        #pragma unroll
        for (int j = 0; j < 8; ++j) {
            float4 v = F4[cb + j * 512 + t];
            __nv_bfloat162 h0 = __float22bfloat162_rn(make_float2(v.x, v.y));
            __nv_bfloat162 h1 = __float22bfloat162_rn(make_float2(v.z, v.w));
            u[j].x = *reinterpret_cast<uint32_t*>(&h0);
            u[j].y = *reinterpret_cast<uint32_t*>(&h1);
        }
    }
    __syncthreads();

    for (int k = 0; k < n; ++k) {
        // ---- stage chunk k into buf k&1 ----
        char* dst = s_A + (k & 1) * (CHUNK * 1024);
        #pragma unroll
        for (int j = 0; j < 8; ++j) {
            int idx = j * 512 + t;                // 0..4095 float4s
            int row = idx >> 7;                   // 128 float4 per row
            int c4  = idx & 127;
            int i16 = c4 >> 1;
            int sw  = (i16 & ~7) | ((i16 ^ row) & 7);
            *reinterpret_cast<uint2*>(dst + row * 1024 + sw * 16 + (c4 & 1) * 8) = u[j];
        }
        __syncthreads();   // S1: staging visible (also orders s_asg[k-1] reduce)

        // ---- prefetch + convert chunk k+1 ----
        if (k + 1 < n) {
            size_t cb = (size_t)(blockIdx.x + (k + 1) * NACC) * (CHUNK * 128);
            #pragma unroll
            for (int j = 0; j < 8; ++j) {
                float4 v = F4[cb + j * 512 + t];
                __nv_bfloat162 h0 = __float22bfloat162_rn(make_float2(v.x, v.y));
                __nv_bfloat162 h1 = __float22bfloat162_rn(make_float2(v.z, v.w));
                u[j].x = *reinterpret_cast<uint32_t*>(&h0);
                u[j].y = *reinterpret_cast<uint32_t*>(&h1);
            }
        }

        // ---- MMA on chunk k (this warp: 16 rows x 8 protos) ----
        {
            uint32_t base = sA0 + (uint32_t)(k & 1) * (CHUNK * 1024);
            float d0 = 0.f, d1 = 0.f, d2 = 0.f, d3 = 0.f;
            #pragma unroll
            for (int ks = 0; ks < 32; ++ks) {
                int i16 = ks * 2 + halfSel;
                int sw = (i16 & ~7) | ((i16 ^ rowB) & 7);
                uint32_t addr = base + rowB * 1024 + sw * 16;
                uint32_t a0, a1, a2, a3;
                asm volatile("ldmatrix.sync.aligned.m8n8.x4.shared.b16 {%0,%1,%2,%3}, [%4];"
                             : "=r"(a0), "=r"(a1), "=r"(a2), "=r"(a3) : "r"(addr));
                asm volatile(
                    "mma.sync.aligned.m16n8k16.row.col.f32.bf16.bf16.f32 "
                    "{%0,%1,%2,%3}, {%4,%5,%6,%7}, {%8,%9}, {%0,%1,%2,%3};"
                    : "+f"(d0), "+f"(d1), "+f"(d2), "+f"(d3)
                    : "r"(a0), "r"(a1), "r"(a2), "r"(a3), "r"(Bf[ks].x), "r"(Bf[ks].y));
            }
            // per-warp argmax over its 8 protos (lane holds cols 2q, 2q+1)
            #pragma unroll
            for (int half = 0; half < 2; ++half) {
                float e0 = half ? d2 : d0;
                float e1 = half ? d3 : d1;
                float bv = e0; int bi = pg * 8 + 2 * q;
                if (e1 > bv) { bv = e1; bi = pg * 8 + 2 * q + 1; }
                #pragma unroll
                for (int off = 1; off <= 2; off <<= 1) {
                    float ov = __shfl_xor_sync(0xffffffffu, bv, off);
                    int   oi = __shfl_xor_sync(0xffffffffu, bi, off);
                    if (ov > bv || (ov == bv && oi < bi)) { bv = ov; bi = oi; }
                }
                if (q == 0) {
                    int r32 = rb * 16 + half * 8 + rg;
                    candV[pg * 32 + r32] = bv;
                    candI[pg * 32 + r32] = bi;
                }
            }
        }

        // ---- accumulate chunk k-1 (same phase: overlaps MMA across warps) ----
        if (k > 0) {
            int pb = (k - 1) & 1;
            const char* src = s_A + pb * (CHUNK * 1024);
            unsigned long long w0 = *reinterpret_cast<const unsigned long long*>(s_asg + pb * 32 + rh * 16);
            unsigned long long w1 = *reinterpret_cast<const unsigned long long*>(s_asg + pb * 32 + rh * 16 + 8);
            #pragma unroll
            for (int j = 0; j < 16; ++j) {
                int r = rh * 16 + j;
                int sw = (i16c & ~7) | ((i16c ^ r) & 7);
                uint32_t hv = *reinterpret_cast<const uint32_t*>(src + r * 1024 + sw * 16 + inoffc);
                __nv_bfloat162 h = *reinterpret_cast<__nv_bfloat162*>(&hv);
                float2 f = __bfloat1622float2(h);
                int a = (int)(((j < 8 ? w0 : w1) >> ((j & 7) * 8)) & 255ull);
                float2 cur = accp[a * (PDIM / 2) + cp];
                cur.x += f.x; cur.y += f.y;
                accp[a * (PDIM / 2) + cp] = cur;
            }
            if (t < NPROTO) {
                #pragma unroll
                for (int jj = 0; jj < 4; ++jj) {
                    unsigned long long x = *reinterpret_cast<const unsigned long long*>(s_asg + pb * 32 + jj * 8);
                    #pragma unroll
                    for (int b = 0; b < 8; ++b)
                        cnt += (int)(((x >> (8 * b)) & 255ull) == (unsigned long long)t);
                }
            }
        }
        __syncthreads();   // S2: cand complete; buf[(k-1)&1] free; s_asg[(k-1)&1] free

        // ---- reduce candidates -> s_asg[k&1] (ascending pg, strict >) ----
        if (t < CHUNK) {
            float bv = candV[t]; int bi = candI[t];
            #pragma unroll
            for (int g = 1; g < 8; ++g) {
                float ov = candV[g * 32 + t];
                if (ov > bv) { bv = ov; bi = candI[g * 32 + t]; }
            }
            s_asg[(k & 1) * 32 + t] = (unsigned char)bi;
        }
        // next iteration's S1 orders this write before its consumers
    }

    __syncthreads();
    // epilogue: accumulate last chunk n-1
    {
        int pb = (n - 1) & 1;
        const char* src = s_A + pb * (CHUNK * 1024);
        unsigned long long w0 = *reinterpret_cast<const unsigned long long*>(s_asg + pb * 32 + rh * 16);
        unsigned long long w1 = *reinterpret_cast<const unsigned long long*>(s_asg + pb * 32 + rh * 16 + 8);
        #pragma unroll
        for (int j = 0; j < 16; ++j) {
            int r = rh * 16 + j;
            int sw = (i16c & ~7) | ((i16c ^ r) & 7);
            uint32_t hv = *reinterpret_cast<const uint32_t*>(src + r * 1024 + sw * 16 + inoffc);
            __nv_bfloat162 h = *reinterpret_cast<__nv_bfloat162*>(&hv);
            float2 f = __bfloat1622float2(h);
            int a = (int)(((j < 8 ? w0 : w1) >> ((j & 7) * 8)) & 255ull);
            float2 cur = accp[a * (PDIM / 2) + cp];
            cur.x += f.x; cur.y += f.y;
            accp[a * (PDIM / 2) + cp] = cur;
        }
        if (t < NPROTO) {
            #pragma unroll
            for (int jj = 0; jj < 4; ++jj) {
                unsigned long long x = *reinterpret_cast<const unsigned long long*>(s_asg + pb * 32 + jj * 8);
                #pragma unroll
                for (int b = 0; b < 8; ++b)
                    cnt += (int)(((x >> (8 * b)) & 255ull) == (unsigned long long)t);
            }
        }
    }
    __syncthreads();

    // deterministic flush of this CTA's partial slice
    float* part = g_Partial + (size_t)blockIdx.x * (NPROTO * PDIM);
    #pragma unroll 4
    for (int k = 0; k < NPROTO; ++k) part[k * PDIM + t] = acc[k * PDIM + t];
    if (t < NPROTO) atomicAdd(&g_Cnt[t], cnt);   // int atomics: deterministic
}

// ---------------- kernel 3: reduce partials + EMA update ----------------
__global__ void finalize_kernel(const float* __restrict__ P, float* __restrict__ out) {
    int k = blockIdx.x >> 3;                          // 64 protos x 8 col-groups
    int t = ((blockIdx.x & 7) << 6) + threadIdx.x;    // 64 threads -> column
    float s = 0.f;
    #pragma unroll 8
    for (int b = 0; b < NACC; ++b)
        s += g_Partial[(size_t)b * (NPROTO * PDIM) + k * PDIM + t];
    int c = g_Cnt[k];
    float p = P[k * PDIM + t];
    float mean = s / fmaxf((float)c, 1.f);
    out[k * PDIM + t] = (c > 0) ? (0.9f * p + 0.1f * mean) : p;
}

// ---------------- launch ----------------
extern "C" void kernel_launch(void* const* d_in, const int* in_sizes, int n_in,
                              void* d_out, int out_size) {
    const float* F = (const float*)d_in[0];
    const float* P = (const float*)d_in[1];
    if (in_sizes[0] == NPROTO * PDIM) {     // robust to input order
        F = (const float*)d_in[1];
        P = (const float*)d_in[0];
    }

    prep_kernel<<<NPROTO, 128>>>(P);

    int smem = NPROTO * PDIM * (int)sizeof(float)   // 128 KB accumulator
             + 2 * CHUNK * 1024                     // 64 KB double-buffered staging
             + 8 * 32 * (int)sizeof(float)          // candV
             + 8 * 32 * (int)sizeof(int)            // candI
             + 64;                                  // s_asg[2][32]
    cudaFuncSetAttribute(fused_kernel, cudaFuncAttributeMaxDynamicSharedMemorySize, smem);
    fused_kernel<<<NACC, 512, smem>>>(F);

    finalize_kernel<<<NPROTO * 8, 64>>>(P, (float*)d_out);
}